// round 1
// baseline (speedup 1.0000x reference)
#include <cuda_runtime.h>
#include <cstdint>

// ---------------------------------------------------------------------------
// ASDHead: out[b,t,n] = sum_h relu(f_proj[b,t,h] + s_proj[b,n,h]) * w[h] + b_head
//   f_proj = features @ W_proj[:256]          (8192 x 128, K=256)
//   s_proj = slots    @ W_proj[256:] + b_proj (8x64 x 128, K=256)
// Strategy: f32x2 packed math everywhere (FFMA2 via PTX), register-resident
// s/w in the elementwise kernel, warp-broadcast shared reads for f.
// ---------------------------------------------------------------------------

#define D_MODEL 256
#define D_HID   128
#define BATCH   8
#define SEQ     1024
#define NSLOT   64
#define MROWS   (BATCH * SEQ)   // 8192

typedef unsigned long long u64;

// -------------------- scratch (static device globals; no allocs) -----------
__device__ float g_fproj[MROWS * D_HID];          // 4 MB
__device__ float g_sproj[BATCH * NSLOT * D_HID];  // 256 KB
__device__ float g_Wt[D_HID * D_MODEL];           // W_f transposed [h][k], 128 KB

// -------------------- f32x2 helpers ----------------------------------------
__device__ __forceinline__ u64 fma2(u64 a, u64 b, u64 c) {
    u64 d;
    asm("fma.rn.f32x2 %0, %1, %2, %3;" : "=l"(d) : "l"(a), "l"(b), "l"(c));
    return d;
}
__device__ __forceinline__ u64 add2(u64 a, u64 b) {
    u64 d;
    asm("add.rn.f32x2 %0, %1, %2;" : "=l"(d) : "l"(a), "l"(b));
    return d;
}
__device__ __forceinline__ u64 pack2(float lo, float hi) {
    u64 r;
    asm("mov.b64 %0, {%1, %2};" : "=l"(r) : "f"(lo), "f"(hi));
    return r;
}
__device__ __forceinline__ void unpack2(u64 v, float& lo, float& hi) {
    asm("mov.b64 {%0, %1}, %2;" : "=f"(lo), "=f"(hi) : "l"(v));
}

union F4U2 {
    float4 f4;
    struct { u64 a, b; } u;
};

// -------------------- K1a: transpose W_f -> g_Wt ---------------------------
// grid 128, block 256.  g_Wt[h][k] = W_proj[k][h], k < 256.
__global__ void k_transpose(const float* __restrict__ Wproj) {
    int h = blockIdx.x;
    int k = threadIdx.x;
    g_Wt[h * D_MODEL + k] = Wproj[k * D_HID + h];
}

// -------------------- K1b: s_proj ------------------------------------------
// grid (64, 8), block 128 (h = tid).
__global__ void __launch_bounds__(128) k_sproj(const float* __restrict__ slots,
                                               const float* __restrict__ Wproj,
                                               const float* __restrict__ bproj) {
    __shared__ float sl[256];
    int n = blockIdx.x, b = blockIdx.y, h = threadIdx.x;
    const float* s = slots + (b * NSLOT + n) * D_MODEL;
    sl[h]       = s[h];
    sl[h + 128] = s[h + 128];
    __syncthreads();
    const float* Ws = Wproj + D_MODEL * D_HID;  // rows 256..511
    float a0 = 0.f, a1 = 0.f, a2v = 0.f, a3 = 0.f;
#pragma unroll 4
    for (int k = 0; k < 256; k += 4) {
        a0  = fmaf(sl[k + 0], Ws[(k + 0) * D_HID + h], a0);
        a1  = fmaf(sl[k + 1], Ws[(k + 1) * D_HID + h], a1);
        a2v = fmaf(sl[k + 2], Ws[(k + 2) * D_HID + h], a2v);
        a3  = fmaf(sl[k + 3], Ws[(k + 3) * D_HID + h], a3);
    }
    g_sproj[(b * NSLOT + n) * D_HID + h] = (a0 + a1) + (a2v + a3) + bproj[h];
}

// -------------------- K2: f_proj GEMM (f32x2, k-pair packed) ---------------
// C[8192,128] = features[8192,256] @ W_f[256,128]
// BM=32, BN=128(full), BK=32.  128 threads. micro-tile 8m x 4n per thread.
// Warp w owns m-rows [8w, 8w+8); lane l owns n in {l, l+32, l+64, l+96}.
// A broadcast across warp; Bs padded to 36 floats/row -> conflict-free phases.
// acc f32x2 halves hold even/odd-k partial sums; summed at writeback.
__global__ void __launch_bounds__(128) k_fproj(const float* __restrict__ features) {
    __shared__ float As[32][36];
    __shared__ float Bs[128][36];
    int tid  = threadIdx.x;
    int warp = tid >> 5;
    int lane = tid & 31;
    int m0   = blockIdx.x * 32;

    u64 acc[8][4];
#pragma unroll
    for (int i = 0; i < 8; i++)
#pragma unroll
        for (int j = 0; j < 4; j++) acc[i][j] = 0ULL;

#pragma unroll 1
    for (int kc = 0; kc < 256; kc += 32) {
        // stage A tile: 256 float4
#pragma unroll
        for (int i = 0; i < 2; i++) {
            int q = i * 128 + tid;
            int row = q >> 3, c4 = (q & 7) * 4;
            float4 v = *(const float4*)(features + (m0 + row) * D_MODEL + kc + c4);
            *(float4*)&As[row][c4] = v;
        }
        // stage B tile: 1024 float4 (Wt is [h][k], k-contiguous)
#pragma unroll
        for (int i = 0; i < 8; i++) {
            int q = i * 128 + tid;
            int row = q >> 3, c4 = (q & 7) * 4;
            float4 v = *(const float4*)(g_Wt + row * D_MODEL + kc + c4);
            *(float4*)&Bs[row][c4] = v;
        }
        __syncthreads();

#pragma unroll
        for (int k4 = 0; k4 < 32; k4 += 4) {
            u64 a2[8][2], b2[4][2];
#pragma unroll
            for (int i = 0; i < 8; i++) {
                F4U2 t;
                t.f4 = *(const float4*)&As[warp * 8 + i][k4];
                a2[i][0] = t.u.a;
                a2[i][1] = t.u.b;
            }
#pragma unroll
            for (int j = 0; j < 4; j++) {
                F4U2 t;
                t.f4 = *(const float4*)&Bs[lane + 32 * j][k4];
                b2[j][0] = t.u.a;
                b2[j][1] = t.u.b;
            }
#pragma unroll
            for (int i = 0; i < 8; i++)
#pragma unroll
                for (int j = 0; j < 4; j++) {
                    acc[i][j] = fma2(a2[i][0], b2[j][0], acc[i][j]);
                    acc[i][j] = fma2(a2[i][1], b2[j][1], acc[i][j]);
                }
        }
        __syncthreads();
    }

#pragma unroll
    for (int i = 0; i < 8; i++)
#pragma unroll
        for (int j = 0; j < 4; j++) {
            float lo, hi;
            unpack2(acc[i][j], lo, hi);
            g_fproj[(m0 + warp * 8 + i) * D_HID + lane + 32 * j] = lo + hi;
        }
}

// -------------------- K3: fused relu-dot -----------------------------------
// grid (32, 8): t-tile of 32 x batch.  256 threads: chunk = tid/64 (32 h's),
// n = tid%64.  s/w register-resident; f tile in shared (warp-broadcast LDS);
// cross-chunk reduction through shared.
__global__ void __launch_bounds__(256) k_out(const float* __restrict__ whead,
                                             const float* __restrict__ bhead,
                                             float* __restrict__ out) {
    __shared__ float fsh[32][128];      // 16 KB
    __shared__ float red[4][32 * 64];   // 32 KB
    int tid   = threadIdx.x;
    int chunk = tid >> 6;
    int n     = tid & 63;
    int b     = blockIdx.y;
    int t0    = blockIdx.x * 32;

    u64 s2[16], w2[16];
    {
        const float* sp = g_sproj + (b * NSLOT + n) * D_HID + chunk * 32;
        const float* wp = whead + chunk * 32;
#pragma unroll
        for (int i = 0; i < 8; i++) {
            F4U2 t;
            t.f4 = *(const float4*)(sp + i * 4);
            s2[2 * i] = t.u.a; s2[2 * i + 1] = t.u.b;
            t.f4 = *(const float4*)(wp + i * 4);
            w2[2 * i] = t.u.a; w2[2 * i + 1] = t.u.b;
        }
    }
    // stage f tile: 32 rows x 128 h = 1024 float4
#pragma unroll
    for (int i = 0; i < 4; i++) {
        int q = i * 256 + tid;
        int row = q >> 5, c4 = (q & 31) * 4;
        *(float4*)&fsh[row][c4] =
            *(const float4*)(g_fproj + (b * SEQ + t0 + row) * D_HID + c4);
    }
    __syncthreads();

#pragma unroll 1
    for (int t = 0; t < 32; t++) {
        const float* fp = &fsh[t][chunk * 32];
        u64 f2[16];
#pragma unroll
        for (int i = 0; i < 8; i++) {
            F4U2 v;
            v.f4 = *(const float4*)(fp + i * 4);
            f2[2 * i] = v.u.a; f2[2 * i + 1] = v.u.b;
        }
        u64 acc[4] = {0ULL, 0ULL, 0ULL, 0ULL};
#pragma unroll
        for (int kk = 0; kk < 16; kk++) {
            u64 x = add2(f2[kk], s2[kk]);
            float lo, hi;
            unpack2(x, lo, hi);
            lo = fmaxf(lo, 0.f);            // FMNMX -> alu pipe (overlaps fma pipe)
            hi = fmaxf(hi, 0.f);
            acc[kk & 3] = fma2(pack2(lo, hi), w2[kk], acc[kk & 3]);
        }
        u64 sA = add2(acc[0], acc[1]);
        u64 sB = add2(acc[2], acc[3]);
        u64 sT = add2(sA, sB);
        float lo, hi;
        unpack2(sT, lo, hi);
        red[chunk][t * 64 + n] = lo + hi;
    }
    __syncthreads();

    float bh = bhead[0];
#pragma unroll
    for (int i = 0; i < 8; i++) {
        int o = i * 256 + tid;
        int t = o >> 6, nn = o & 63;
        out[(b * SEQ + t0 + t) * NSLOT + nn] =
            red[0][o] + red[1][o] + red[2][o] + red[3][o] + bh;
    }
}

// -------------------- launch -----------------------------------------------
extern "C" void kernel_launch(void* const* d_in, const int* in_sizes, int n_in,
                              void* d_out, int out_size) {
    const float* features = (const float*)d_in[0];  // (8,1024,256)
    const float* slots    = (const float*)d_in[1];  // (8,64,256)
    const float* W_proj   = (const float*)d_in[2];  // (512,128)
    const float* b_proj   = (const float*)d_in[3];  // (128)
    const float* w_head   = (const float*)d_in[4];  // (128)
    const float* b_head   = (const float*)d_in[5];  // (1)
    float* out = (float*)d_out;                     // (8,1024,64)

    k_transpose<<<128, 256>>>(W_proj);
    k_sproj<<<dim3(64, 8), 128>>>(slots, W_proj, b_proj);
    k_fproj<<<MROWS / 32, 128>>>(features);
    k_out<<<dim3(32, 8), 256>>>(w_head, b_head, out);
}